// round 9
// baseline (speedup 1.0000x reference)
#include <cuda_runtime.h>
#include <cuda_fp16.h>
#include <stdint.h>

#define NN 50000
#define NE 800000
#define DD 64

#define SCAN_T 1024
#define NCHUNK ((NN + SCAN_T - 1) / SCAN_T)   // 49

// scratch (no allocations allowed). Zero-initialized at module load.
// INVARIANT: g_cnt == 0 at entry of every kernel_launch call (fill_kernel
// resets it each call via the pos==0 edge).
__device__ __half g_xh[NN * DD];     // fp16 copy of x
__device__ __half g_y0h[NN * DD];    // fp16 layer-0 output
__device__ int    g_cnt[NN];
__device__ int    g_rowptr[NN + 1];
__device__ int    g_col[NE];
__device__ int    g_pos[NE];

// ---------------------------------------------------------------------------
// fused conv (x -> fp16) + degree histogram (records per-edge slot)
// ---------------------------------------------------------------------------
__global__ void __launch_bounds__(256)
convhist_kernel(const float* __restrict__ x, const int* __restrict__ dst) {
    int i = blockIdx.x * blockDim.x + threadIdx.x;
    if (i < NN * DD / 8) {
        float4 a = ((const float4*)x)[2 * i];
        float4 b = ((const float4*)x)[2 * i + 1];
        __half2 h[4];
        h[0] = __floats2half2_rn(a.x, a.y);
        h[1] = __floats2half2_rn(a.z, a.w);
        h[2] = __floats2half2_rn(b.x, b.y);
        h[3] = __floats2half2_rn(b.z, b.w);
        ((uint4*)g_xh)[i] = *(uint4*)h;
    }
    if (i < NE) {
        g_pos[i] = atomicAdd(&g_cnt[dst[i]], 1);
    }
}

// ---------------------------------------------------------------------------
// single-pass scan: block b block-reduces chunks [0,b) for its base offset
// (L2-hot, redundant), then inclusive-scans its own chunk. Does NOT zero g_cnt.
// ---------------------------------------------------------------------------
__global__ void __launch_bounds__(SCAN_T)
scan_kernel() {
    __shared__ int s[SCAN_T];
    __shared__ int s_base;
    int b = blockIdx.x;
    int t = threadIdx.x;

    // base = sum of all preceding chunks
    int pre = 0;
    for (int i = t; i < b * SCAN_T; i += SCAN_T) pre += g_cnt[i];
    s[t] = pre;
    __syncthreads();
    #pragma unroll
    for (int off = SCAN_T / 2; off > 0; off >>= 1) {
        if (t < off) s[t] += s[t + off];
        __syncthreads();
    }
    if (t == 0) s_base = s[0];
    __syncthreads();
    int base = s_base;
    __syncthreads();

    // inclusive scan of own chunk
    int i = b * SCAN_T + t;
    int v = (i < NN) ? g_cnt[i] : 0;
    s[t] = v;
    __syncthreads();
    #pragma unroll
    for (int off = 1; off < SCAN_T; off <<= 1) {
        int add = (t >= off) ? s[t - off] : 0;
        __syncthreads();
        s[t] += add;
        __syncthreads();
    }
    if (i < NN) g_rowptr[i + 1] = base + s[t];
    if (i == 0) g_rowptr[0] = 0;
}

// atomic-free fill; pos==0 edge resets g_cnt[d] for the next call
__global__ void fill_kernel(const int* __restrict__ src,
                            const int* __restrict__ dst) {
    int e = blockIdx.x * blockDim.x + threadIdx.x;
    if (e < NE) {
        int d = dst[e];
        int p = g_pos[e];
        g_col[g_rowptr[d] + p] = src[e];
        if (p == 0) g_cnt[d] = 0;
    }
}

// ---------------------------------------------------------------------------
// fused GIN layer: gather (fp16 in, fp32 acc) directly into smem, then MLP.
// block = 128 threads, 64-node tile.
// gather: 8 lanes/node (8 halfs each), 4 node-groups of 16.
// MLP: thread (ng,cg) owns rows {ng+16j}, cols [8cg,8cg+8).
// ---------------------------------------------------------------------------
__device__ __forceinline__ float fast_tanh(float x) {
    float y;
    asm("tanh.approx.f32 %0, %1;" : "=f"(y) : "f"(x));
    return y;
}

__device__ __forceinline__ void acc_add(float* a, uint4 v) {
    const __half2* h = (const __half2*)&v;
    #pragma unroll
    for (int i = 0; i < 4; i++) {
        float2 f = __half22float2(h[i]);
        a[2 * i]     += f.x;
        a[2 * i + 1] += f.y;
    }
}

#define T_STRIDE 65
#define SMEM_FLOATS (4096 * 2 + 64 * T_STRIDE)   // 49408 B

__global__ void __launch_bounds__(128, 4)
layer_kernel(const float* __restrict__ w1, const float* __restrict__ b1,
             const float* __restrict__ w2, const float* __restrict__ b2,
             float* __restrict__ out, int in_scratch, int out_half) {
    extern __shared__ float sm[];
    float* sW1 = sm;                    // 64*64
    float* sW2 = sm + 4096;             // 64*64
    float* sT  = sm + 8192;             // 64 * T_STRIDE (tile, then tanh(h))

    const __half* __restrict__ base = in_scratch ? g_y0h : g_xh;

    const int tid = threadIdx.x;
    const int n0 = blockIdx.x * 64;

    // ---- load weights into smem (overlaps with gather latency) ----
    #pragma unroll
    for (int rep = 0; rep < 8; rep++) {
        int f4 = rep * 128 + tid;
        ((float4*)sW1)[f4] = ((const float4*)w1)[f4];
        ((float4*)sW2)[f4] = ((const float4*)w2)[f4];
    }

    // ---- gather: sT[n] = X[n] + sum_{j in N(n)} X[j] ----
    {
        const int sub = tid & 7;          // 8 halfs per lane
        const int nl  = tid >> 3;         // 0..15
        const int colh = sub << 3;
        #pragma unroll
        for (int g = 0; g < 4; g++) {
            int nloc = g * 16 + nl;
            int node = n0 + nloc;
            float acc[8] = {0.f, 0.f, 0.f, 0.f, 0.f, 0.f, 0.f, 0.f};
            if (node < NN) {
                acc_add(acc, *(const uint4*)(base + (size_t)node * DD + colh));
                int p   = g_rowptr[node];
                int end = g_rowptr[node + 1];
                for (; p + 3 < end; p += 4) {
                    int j0 = g_col[p];
                    int j1 = g_col[p + 1];
                    int j2 = g_col[p + 2];
                    int j3 = g_col[p + 3];
                    uint4 a = *(const uint4*)(base + (size_t)j0 * DD + colh);
                    uint4 b = *(const uint4*)(base + (size_t)j1 * DD + colh);
                    uint4 c = *(const uint4*)(base + (size_t)j2 * DD + colh);
                    uint4 d = *(const uint4*)(base + (size_t)j3 * DD + colh);
                    acc_add(acc, a);
                    acc_add(acc, b);
                    acc_add(acc, c);
                    acc_add(acc, d);
                }
                for (; p < end; p++) {
                    uint4 a = *(const uint4*)(base + (size_t)g_col[p] * DD + colh);
                    acc_add(acc, a);
                }
            }
            float* pT = sT + nloc * T_STRIDE + colh;
            #pragma unroll
            for (int u = 0; u < 8; u++) pT[u] = acc[u];
        }
    }
    __syncthreads();

    const int ng = tid & 15;
    const int cg = tid >> 4;
    const int cb = cg * 8;

    float acc[4][8];

    // ---- GEMM1: h = T @ W1 + b1 ----
    {
        float bv[8];
        #pragma unroll
        for (int u = 0; u < 8; u++) bv[u] = b1[cb + u];
        #pragma unroll
        for (int j = 0; j < 4; j++)
            #pragma unroll
            for (int u = 0; u < 8; u++) acc[j][u] = bv[u];

        #pragma unroll 4
        for (int k = 0; k < 64; k++) {
            float4 wA = *(const float4*)(sW1 + k * 64 + cb);
            float4 wB = *(const float4*)(sW1 + k * 64 + cb + 4);
            float w[8] = {wA.x, wA.y, wA.z, wA.w, wB.x, wB.y, wB.z, wB.w};
            #pragma unroll
            for (int j = 0; j < 4; j++) {
                float tv = sT[(ng + 16 * j) * T_STRIDE + k];
                #pragma unroll
                for (int u = 0; u < 8; u++) acc[j][u] += tv * w[u];
            }
        }
    }

    // ---- tanh; overwrite sT ----
    __syncthreads();
    #pragma unroll
    for (int j = 0; j < 4; j++) {
        float* hrow = sT + (ng + 16 * j) * T_STRIDE + cb;
        #pragma unroll
        for (int u = 0; u < 8; u++)
            hrow[u] = fast_tanh(acc[j][u]);
    }
    __syncthreads();

    // ---- GEMM2: y = H @ W2 + b2 ----
    {
        float bv[8];
        #pragma unroll
        for (int u = 0; u < 8; u++) bv[u] = b2[cb + u];
        #pragma unroll
        for (int j = 0; j < 4; j++)
            #pragma unroll
            for (int u = 0; u < 8; u++) acc[j][u] = bv[u];

        #pragma unroll 4
        for (int k = 0; k < 64; k++) {
            float4 wA = *(const float4*)(sW2 + k * 64 + cb);
            float4 wB = *(const float4*)(sW2 + k * 64 + cb + 4);
            float w[8] = {wA.x, wA.y, wA.z, wA.w, wB.x, wB.y, wB.z, wB.w};
            #pragma unroll
            for (int j = 0; j < 4; j++) {
                float hv = sT[(ng + 16 * j) * T_STRIDE + k];
                #pragma unroll
                for (int u = 0; u < 8; u++) acc[j][u] += hv * w[u];
            }
        }
    }

    // ---- store ----
    #pragma unroll
    for (int j = 0; j < 4; j++) {
        int n = n0 + ng + 16 * j;
        if (n < NN) {
            if (out_half) {
                __half2 h[4];
                h[0] = __floats2half2_rn(acc[j][0], acc[j][1]);
                h[1] = __floats2half2_rn(acc[j][2], acc[j][3]);
                h[2] = __floats2half2_rn(acc[j][4], acc[j][5]);
                h[3] = __floats2half2_rn(acc[j][6], acc[j][7]);
                *(uint4*)(g_y0h + (size_t)n * DD + cb) = *(uint4*)h;
            } else {
                *(float4*)(out + (size_t)n * DD + cb) =
                    make_float4(acc[j][0], acc[j][1], acc[j][2], acc[j][3]);
                *(float4*)(out + (size_t)n * DD + cb + 4) =
                    make_float4(acc[j][4], acc[j][5], acc[j][6], acc[j][7]);
            }
        }
    }
}

// ---------------------------------------------------------------------------
// launch — 5 kernels total
// ---------------------------------------------------------------------------
extern "C" void kernel_launch(void* const* d_in, const int* in_sizes, int n_in,
                              void* d_out, int out_size) {
    const float* x    = (const float*)d_in[0];
    const int*   src  = (const int*)d_in[1];
    const int*   dst  = (const int*)d_in[2];
    const float* w1_0 = (const float*)d_in[3];
    const float* b1_0 = (const float*)d_in[4];
    const float* w2_0 = (const float*)d_in[5];
    const float* b2_0 = (const float*)d_in[6];
    const float* w1_1 = (const float*)d_in[7];
    const float* b1_1 = (const float*)d_in[8];
    const float* w2_1 = (const float*)d_in[9];
    const float* b2_1 = (const float*)d_in[10];
    float* out = (float*)d_out;

    const int smem_bytes = SMEM_FLOATS * sizeof(float);
    cudaFuncSetAttribute(layer_kernel, cudaFuncAttributeMaxDynamicSharedMemorySize,
                         smem_bytes);

    const int edgeb = (NE + 255) / 256;           // covers conv range too
    const int tileb = (NN + 63) / 64;             // 782

    convhist_kernel<<<edgeb, 256>>>(x, dst);
    scan_kernel<<<NCHUNK, SCAN_T>>>();
    fill_kernel<<<edgeb, 256>>>(src, dst);

    layer_kernel<<<tileb, 128, smem_bytes>>>(w1_0, b1_0, w2_0, b2_0,
                                             out, /*in_scratch=*/0, /*out_half=*/1);
    layer_kernel<<<tileb, 128, smem_bytes>>>(w1_1, b1_1, w2_1, b2_1,
                                             out, /*in_scratch=*/1, /*out_half=*/0);
}

// round 10
// speedup vs baseline: 1.1585x; 1.1585x over previous
#include <cuda_runtime.h>
#include <cuda_fp16.h>
#include <stdint.h>

#define NN 50000
#define NE 800000
#define DD 64

#define SCAN_T 1024
#define NCHUNK ((NN + SCAN_T - 1) / SCAN_T)   // 49

// scratch (no allocations allowed). Zero-initialized at module load.
// INVARIANT: g_cnt == 0 at entry of every kernel_launch call (fill_kernel
// resets it each call via the pos==0 edge).
__device__ float  g_agg[NN * DD];    // h_in = x + sum(neighbors), fp32
__device__ __half g_xh[NN * DD];     // fp16 copy of x
__device__ __half g_y0h[NN * DD];    // fp16 layer-0 output
__device__ int    g_cnt[NN];
__device__ int    g_rowptr[NN + 1];
__device__ int    g_col[NE];
__device__ int    g_pos[NE];

// ---------------------------------------------------------------------------
// fused conv (x -> fp16) + degree histogram (records per-edge slot)
// ---------------------------------------------------------------------------
__global__ void __launch_bounds__(256)
convhist_kernel(const float* __restrict__ x, const int* __restrict__ dst) {
    int i = blockIdx.x * blockDim.x + threadIdx.x;
    if (i < NN * DD / 8) {
        float4 a = ((const float4*)x)[2 * i];
        float4 b = ((const float4*)x)[2 * i + 1];
        __half2 h[4];
        h[0] = __floats2half2_rn(a.x, a.y);
        h[1] = __floats2half2_rn(a.z, a.w);
        h[2] = __floats2half2_rn(b.x, b.y);
        h[3] = __floats2half2_rn(b.z, b.w);
        ((uint4*)g_xh)[i] = *(uint4*)h;
    }
    if (i < NE) {
        g_pos[i] = atomicAdd(&g_cnt[dst[i]], 1);
    }
}

// ---------------------------------------------------------------------------
// single-pass scan: block b block-reduces chunks [0,b) for its base offset
// (L2-hot, redundant), then inclusive-scans its own chunk. Does NOT zero g_cnt.
// ---------------------------------------------------------------------------
__global__ void __launch_bounds__(SCAN_T)
scan_kernel() {
    __shared__ int s[SCAN_T];
    __shared__ int s_base;
    int b = blockIdx.x;
    int t = threadIdx.x;

    int pre = 0;
    for (int i = t; i < b * SCAN_T; i += SCAN_T) pre += g_cnt[i];
    s[t] = pre;
    __syncthreads();
    #pragma unroll
    for (int off = SCAN_T / 2; off > 0; off >>= 1) {
        if (t < off) s[t] += s[t + off];
        __syncthreads();
    }
    if (t == 0) s_base = s[0];
    __syncthreads();
    int base = s_base;
    __syncthreads();

    int i = b * SCAN_T + t;
    int v = (i < NN) ? g_cnt[i] : 0;
    s[t] = v;
    __syncthreads();
    #pragma unroll
    for (int off = 1; off < SCAN_T; off <<= 1) {
        int add = (t >= off) ? s[t - off] : 0;
        __syncthreads();
        s[t] += add;
        __syncthreads();
    }
    if (i < NN) g_rowptr[i + 1] = base + s[t];
    if (i == 0) g_rowptr[0] = 0;
}

// atomic-free fill; pos==0 edge resets g_cnt[d] for the next call
__global__ void fill_kernel(const int* __restrict__ src,
                            const int* __restrict__ dst) {
    int e = blockIdx.x * blockDim.x + threadIdx.x;
    if (e < NE) {
        int d = dst[e];
        int p = g_pos[e];
        g_col[g_rowptr[d] + p] = src[e];
        if (p == 0) g_cnt[d] = 0;
    }
}

// ---------------------------------------------------------------------------
// fp16 gather (high occupancy, standalone): g_agg[n] = X[n] + sum X[j]
// 8 lanes per node, each lane owns 8 halfs (16B), 4-wide neighbor unroll.
// ---------------------------------------------------------------------------
__device__ __forceinline__ void acc_add(float* a, uint4 v) {
    const __half2* h = (const __half2*)&v;
    #pragma unroll
    for (int i = 0; i < 4; i++) {
        float2 f = __half22float2(h[i]);
        a[2 * i]     += f.x;
        a[2 * i + 1] += f.y;
    }
}

__global__ void __launch_bounds__(256)
gather_kernel(int in_scratch) {
    const __half* __restrict__ base = in_scratch ? g_y0h : g_xh;
    int t = blockIdx.x * blockDim.x + threadIdx.x;
    int node = t >> 3;
    if (node >= NN) return;
    int colh = (t & 7) << 3;

    float acc[8] = {0.f};
    acc_add(acc, *(const uint4*)(base + (size_t)node * DD + colh));

    int p   = g_rowptr[node];
    int end = g_rowptr[node + 1];

    for (; p + 3 < end; p += 4) {
        int j0 = g_col[p];
        int j1 = g_col[p + 1];
        int j2 = g_col[p + 2];
        int j3 = g_col[p + 3];
        uint4 a = *(const uint4*)(base + (size_t)j0 * DD + colh);
        uint4 b = *(const uint4*)(base + (size_t)j1 * DD + colh);
        uint4 c = *(const uint4*)(base + (size_t)j2 * DD + colh);
        uint4 d = *(const uint4*)(base + (size_t)j3 * DD + colh);
        acc_add(acc, a);
        acc_add(acc, b);
        acc_add(acc, c);
        acc_add(acc, d);
    }
    for (; p < end; p++) {
        uint4 a = *(const uint4*)(base + (size_t)g_col[p] * DD + colh);
        acc_add(acc, a);
    }

    float* o = g_agg + (size_t)node * DD + colh;
    *(float4*)o       = make_float4(acc[0], acc[1], acc[2], acc[3]);
    *(float4*)(o + 4) = make_float4(acc[4], acc[5], acc[6], acc[7]);
}

// ---------------------------------------------------------------------------
// MLP (scalar FFMA, single weight buffer for occupancy):
//   out = tanh(g_agg @ W1 + b1) @ W2 + b2
// smem = sW[4096] + sT[64*65] = 33 KB -> 6 blocks/SM (50% occ).
// ---------------------------------------------------------------------------
__device__ __forceinline__ float fast_tanh(float x) {
    float y;
    asm("tanh.approx.f32 %0, %1;" : "=f"(y) : "f"(x));
    return y;
}

#define T_STRIDE 65
#define SMEM_FLOATS (4096 + 64 * T_STRIDE)   // 8256 floats = 33024 B

__global__ void __launch_bounds__(128, 6)
mlp_kernel(const float* __restrict__ w1, const float* __restrict__ b1,
           const float* __restrict__ w2, const float* __restrict__ b2,
           float* __restrict__ out, int out_half) {
    extern __shared__ float sm[];
    float* sW = sm;                    // 64*64 (W1 then W2)
    float* sT = sm + 4096;             // 64 * T_STRIDE (tile, then tanh(h))

    const int tid = threadIdx.x;
    const int n0 = blockIdx.x * 64;

    // ---- load W1 + node tile ----
    #pragma unroll
    for (int rep = 0; rep < 8; rep++) {
        int f4 = rep * 128 + tid;
        ((float4*)sW)[f4] = ((const float4*)w1)[f4];
    }
    #pragma unroll
    for (int rep = 0; rep < 8; rep++) {
        int f4 = rep * 128 + tid;
        int n = f4 >> 4;
        int k = (f4 & 15) << 2;
        float4 v;
        if (n0 + n < NN) {
            v = *(const float4*)(g_agg + (size_t)(n0 + n) * DD + k);
        } else {
            v = make_float4(0.f, 0.f, 0.f, 0.f);
        }
        float* p = sT + n * T_STRIDE + k;
        p[0] = v.x; p[1] = v.y; p[2] = v.z; p[3] = v.w;
    }
    __syncthreads();

    const int ng = tid & 15;
    const int cg = tid >> 4;
    const int cb = cg * 8;

    float acc[4][8];

    // ---- GEMM1: h = T @ W1 + b1 ----
    {
        float bv[8];
        #pragma unroll
        for (int u = 0; u < 8; u++) bv[u] = b1[cb + u];
        #pragma unroll
        for (int j = 0; j < 4; j++)
            #pragma unroll
            for (int u = 0; u < 8; u++) acc[j][u] = bv[u];

        #pragma unroll 4
        for (int k = 0; k < 64; k++) {
            float4 wA = *(const float4*)(sW + k * 64 + cb);
            float4 wB = *(const float4*)(sW + k * 64 + cb + 4);
            float w[8] = {wA.x, wA.y, wA.z, wA.w, wB.x, wB.y, wB.z, wB.w};
            #pragma unroll
            for (int j = 0; j < 4; j++) {
                float tv = sT[(ng + 16 * j) * T_STRIDE + k];
                #pragma unroll
                for (int u = 0; u < 8; u++) acc[j][u] += tv * w[u];
            }
        }
    }

    // ---- everyone done with W1 and sT; overwrite both ----
    __syncthreads();
    #pragma unroll
    for (int rep = 0; rep < 8; rep++) {
        int f4 = rep * 128 + tid;
        ((float4*)sW)[f4] = ((const float4*)w2)[f4];
    }
    #pragma unroll
    for (int j = 0; j < 4; j++) {
        float* hrow = sT + (ng + 16 * j) * T_STRIDE + cb;
        #pragma unroll
        for (int u = 0; u < 8; u++)
            hrow[u] = fast_tanh(acc[j][u]);
    }
    __syncthreads();

    // ---- GEMM2: y = H @ W2 + b2 ----
    {
        float bv[8];
        #pragma unroll
        for (int u = 0; u < 8; u++) bv[u] = b2[cb + u];
        #pragma unroll
        for (int j = 0; j < 4; j++)
            #pragma unroll
            for (int u = 0; u < 8; u++) acc[j][u] = bv[u];

        #pragma unroll 4
        for (int k = 0; k < 64; k++) {
            float4 wA = *(const float4*)(sW + k * 64 + cb);
            float4 wB = *(const float4*)(sW + k * 64 + cb + 4);
            float w[8] = {wA.x, wA.y, wA.z, wA.w, wB.x, wB.y, wB.z, wB.w};
            #pragma unroll
            for (int j = 0; j < 4; j++) {
                float hv = sT[(ng + 16 * j) * T_STRIDE + k];
                #pragma unroll
                for (int u = 0; u < 8; u++) acc[j][u] += hv * w[u];
            }
        }
    }

    // ---- store ----
    #pragma unroll
    for (int j = 0; j < 4; j++) {
        int n = n0 + ng + 16 * j;
        if (n < NN) {
            if (out_half) {
                __half2 h[4];
                h[0] = __floats2half2_rn(acc[j][0], acc[j][1]);
                h[1] = __floats2half2_rn(acc[j][2], acc[j][3]);
                h[2] = __floats2half2_rn(acc[j][4], acc[j][5]);
                h[3] = __floats2half2_rn(acc[j][6], acc[j][7]);
                *(uint4*)(g_y0h + (size_t)n * DD + cb) = *(uint4*)h;
            } else {
                *(float4*)(out + (size_t)n * DD + cb) =
                    make_float4(acc[j][0], acc[j][1], acc[j][2], acc[j][3]);
                *(float4*)(out + (size_t)n * DD + cb + 4) =
                    make_float4(acc[j][4], acc[j][5], acc[j][6], acc[j][7]);
            }
        }
    }
}

// ---------------------------------------------------------------------------
// launch — 7 kernels
// ---------------------------------------------------------------------------
extern "C" void kernel_launch(void* const* d_in, const int* in_sizes, int n_in,
                              void* d_out, int out_size) {
    const float* x    = (const float*)d_in[0];
    const int*   src  = (const int*)d_in[1];
    const int*   dst  = (const int*)d_in[2];
    const float* w1_0 = (const float*)d_in[3];
    const float* b1_0 = (const float*)d_in[4];
    const float* w2_0 = (const float*)d_in[5];
    const float* b2_0 = (const float*)d_in[6];
    const float* w1_1 = (const float*)d_in[7];
    const float* b1_1 = (const float*)d_in[8];
    const float* w2_1 = (const float*)d_in[9];
    const float* b2_1 = (const float*)d_in[10];
    float* out = (float*)d_out;

    const int smem_bytes = SMEM_FLOATS * sizeof(float);   // 33024 B
    cudaFuncSetAttribute(mlp_kernel, cudaFuncAttributeMaxDynamicSharedMemorySize,
                         smem_bytes);

    const int edgeb = (NE + 255) / 256;
    const int gathb = (NN * 8 + 255) / 256;
    const int mlpb  = (NN + 63) / 64;

    convhist_kernel<<<edgeb, 256>>>(x, dst);
    scan_kernel<<<NCHUNK, SCAN_T>>>();
    fill_kernel<<<edgeb, 256>>>(src, dst);

    gather_kernel<<<gathb, 256>>>(/*in_scratch=*/0);
    mlp_kernel<<<mlpb, 128, smem_bytes>>>(w1_0, b1_0, w2_0, b2_0,
                                          out, /*out_half=*/1);

    gather_kernel<<<gathb, 256>>>(/*in_scratch=*/1);
    mlp_kernel<<<mlpb, 128, smem_bytes>>>(w1_1, b1_1, w2_1, b2_1,
                                          out, /*out_half=*/0);
}

// round 11
// speedup vs baseline: 1.6393x; 1.4150x over previous
#include <cuda_runtime.h>
#include <cuda_fp16.h>
#include <stdint.h>

#define NN 50000
#define NE 800000
#define DD 64

#define SCAN_T 1024
#define NCHUNK ((NN + SCAN_T - 1) / SCAN_T)   // 49

// scratch (no allocations allowed). Zero-initialized at module load.
// INVARIANT: g_cnt == 0 at entry of every kernel_launch call.
__device__ __half g_aggh[NN * DD];   // h_in = x + sum(neighbors), fp16
__device__ __half g_xh[NN * DD];     // fp16 copy of x
__device__ __half g_y0h[NN * DD];    // fp16 layer-0 output
__device__ int    g_cnt[NN];
__device__ int    g_rowptr[NN + 1];
__device__ int    g_col[NE];
__device__ int    g_pos[NE];

// ---------------------------------------------------------------------------
// fused conv (x -> fp16) + degree histogram (records per-edge slot)
// ---------------------------------------------------------------------------
__global__ void __launch_bounds__(256)
convhist_kernel(const float* __restrict__ x, const int* __restrict__ dst) {
    int i = blockIdx.x * blockDim.x + threadIdx.x;
    if (i < NN * DD / 8) {
        float4 a = ((const float4*)x)[2 * i];
        float4 b = ((const float4*)x)[2 * i + 1];
        __half2 h[4];
        h[0] = __floats2half2_rn(a.x, a.y);
        h[1] = __floats2half2_rn(a.z, a.w);
        h[2] = __floats2half2_rn(b.x, b.y);
        h[3] = __floats2half2_rn(b.z, b.w);
        ((uint4*)g_xh)[i] = *(uint4*)h;
    }
    if (i < NE) {
        g_pos[i] = atomicAdd(&g_cnt[dst[i]], 1);
    }
}

// ---------------------------------------------------------------------------
// single-pass scan (block b redundantly reduces chunks [0,b) for its base)
// ---------------------------------------------------------------------------
__global__ void __launch_bounds__(SCAN_T)
scan_kernel() {
    __shared__ int s[SCAN_T];
    __shared__ int s_base;
    int b = blockIdx.x;
    int t = threadIdx.x;

    int pre = 0;
    for (int i = t; i < b * SCAN_T; i += SCAN_T) pre += g_cnt[i];
    s[t] = pre;
    __syncthreads();
    #pragma unroll
    for (int off = SCAN_T / 2; off > 0; off >>= 1) {
        if (t < off) s[t] += s[t + off];
        __syncthreads();
    }
    if (t == 0) s_base = s[0];
    __syncthreads();
    int base = s_base;
    __syncthreads();

    int i = b * SCAN_T + t;
    int v = (i < NN) ? g_cnt[i] : 0;
    s[t] = v;
    __syncthreads();
    #pragma unroll
    for (int off = 1; off < SCAN_T; off <<= 1) {
        int add = (t >= off) ? s[t - off] : 0;
        __syncthreads();
        s[t] += add;
        __syncthreads();
    }
    if (i < NN) g_rowptr[i + 1] = base + s[t];
    if (i == 0) g_rowptr[0] = 0;
}

// atomic-free fill; pos==0 edge resets g_cnt[d] for the next call
__global__ void fill_kernel(const int* __restrict__ src,
                            const int* __restrict__ dst) {
    int e = blockIdx.x * blockDim.x + threadIdx.x;
    if (e < NE) {
        int d = dst[e];
        int p = g_pos[e];
        g_col[g_rowptr[d] + p] = src[e];
        if (p == 0) g_cnt[d] = 0;
    }
}

// ---------------------------------------------------------------------------
// fp16 gather: g_aggh[n] = X[n] + sum X[j]  (fp16 in, fp32 acc, fp16 out)
// ---------------------------------------------------------------------------
__device__ __forceinline__ void acc_add(float* a, uint4 v) {
    const __half2* h = (const __half2*)&v;
    #pragma unroll
    for (int i = 0; i < 4; i++) {
        float2 f = __half22float2(h[i]);
        a[2 * i]     += f.x;
        a[2 * i + 1] += f.y;
    }
}

__global__ void __launch_bounds__(256)
gather_kernel(int in_scratch) {
    const __half* __restrict__ base = in_scratch ? g_y0h : g_xh;
    int t = blockIdx.x * blockDim.x + threadIdx.x;
    int node = t >> 3;
    if (node >= NN) return;
    int colh = (t & 7) << 3;

    float acc[8] = {0.f};
    acc_add(acc, *(const uint4*)(base + (size_t)node * DD + colh));

    int p   = g_rowptr[node];
    int end = g_rowptr[node + 1];

    for (; p + 3 < end; p += 4) {
        int j0 = g_col[p];
        int j1 = g_col[p + 1];
        int j2 = g_col[p + 2];
        int j3 = g_col[p + 3];
        uint4 a = *(const uint4*)(base + (size_t)j0 * DD + colh);
        uint4 b = *(const uint4*)(base + (size_t)j1 * DD + colh);
        uint4 c = *(const uint4*)(base + (size_t)j2 * DD + colh);
        uint4 d = *(const uint4*)(base + (size_t)j3 * DD + colh);
        acc_add(acc, a);
        acc_add(acc, b);
        acc_add(acc, c);
        acc_add(acc, d);
    }
    for (; p < end; p++) {
        uint4 a = *(const uint4*)(base + (size_t)g_col[p] * DD + colh);
        acc_add(acc, a);
    }

    __half2 h[4];
    h[0] = __floats2half2_rn(acc[0], acc[1]);
    h[1] = __floats2half2_rn(acc[2], acc[3]);
    h[2] = __floats2half2_rn(acc[4], acc[5]);
    h[3] = __floats2half2_rn(acc[6], acc[7]);
    *(uint4*)(g_aggh + (size_t)node * DD + colh) = *(uint4*)h;
}

// ---------------------------------------------------------------------------
// HMMA MLP: out = tanh(T @ W1 + b1) @ W2 + b2 on fp16 tensor cores, f32 acc.
// block = 128 threads (4 warps), tile = 64 nodes; warp w owns rows 16w..16w+15.
// GEMM1 C-fragments ARE GEMM2 A-fragments (same index layout) -> tanh+repack
// entirely in registers, no smem round-trip between GEMMs.
// ---------------------------------------------------------------------------
__device__ __forceinline__ float fast_tanh(float x) {
    float y;
    asm("tanh.approx.f32 %0, %1;" : "=f"(y) : "f"(x));
    return y;
}

__device__ __forceinline__ void hmma(float* c, const uint32_t* a,
                                     uint32_t b0, uint32_t b1) {
    asm volatile(
        "mma.sync.aligned.m16n8k16.row.col.f32.f16.f16.f32 "
        "{%0,%1,%2,%3},{%4,%5,%6,%7},{%8,%9},{%0,%1,%2,%3};"
        : "+f"(c[0]), "+f"(c[1]), "+f"(c[2]), "+f"(c[3])
        : "r"(a[0]), "r"(a[1]), "r"(a[2]), "r"(a[3]), "r"(b0), "r"(b1));
}

__device__ __forceinline__ uint32_t pack_h2(float lo, float hi) {
    __half2 h = __floats2half2_rn(lo, hi);
    return *(uint32_t*)&h;
}

#define WS 72   // padded half-stride (144B rows; conflict-free frag loads)

__global__ void __launch_bounds__(128)
mlp_kernel(const float* __restrict__ w1, const float* __restrict__ b1,
           const float* __restrict__ w2, const float* __restrict__ b2,
           float* __restrict__ out, int out_half) {
    __shared__ __half sW1t[64 * WS];   // sW1t[n][k] = W1[k][n]
    __shared__ __half sW2t[64 * WS];
    __shared__ __half sT[64 * WS];     // node tile, row-major fp16

    const int tid = threadIdx.x;
    const int n0 = blockIdx.x * 64;

    // ---- stage W1^T, W2^T (coalesced global reads; once per block) ----
    #pragma unroll 8
    for (int i = 0; i < 32; i++) {
        int id = i * 128 + tid;        // 4096 elements
        int k = id >> 6, n = id & 63;
        sW1t[n * WS + k] = __float2half(w1[id]);
        sW2t[n * WS + k] = __float2half(w2[id]);
    }

    // ---- stage node tile (fp16, 16B chunks) ----
    #pragma unroll
    for (int i = 0; i < 4; i++) {
        int u4 = i * 128 + tid;        // 512 uint4 over 64x64 halves
        int n = u4 >> 3;
        int c = (u4 & 7) * 8;
        uint4 v = make_uint4(0, 0, 0, 0);
        if (n0 + n < NN)
            v = *(const uint4*)(g_aggh + (size_t)(n0 + n) * DD + c);
        *(uint4*)(sT + n * WS + c) = v;
    }
    __syncthreads();

    const int w = tid >> 5;
    const int lane = tid & 31;
    const int g = lane >> 2;     // 0..7
    const int tg = lane & 3;     // 0..3
    const int row0 = w * 16 + g;
    const int row1 = row0 + 8;

    // ---- A fragments for GEMM1 (4 k-tiles) ----
    uint32_t a1f[4][4];
    #pragma unroll
    for (int kt = 0; kt < 4; kt++) {
        int k0 = kt * 16 + tg * 2;
        a1f[kt][0] = *(const uint32_t*)(sT + row0 * WS + k0);
        a1f[kt][1] = *(const uint32_t*)(sT + row1 * WS + k0);
        a1f[kt][2] = *(const uint32_t*)(sT + row0 * WS + k0 + 8);
        a1f[kt][3] = *(const uint32_t*)(sT + row1 * WS + k0 + 8);
    }

    float acc[8][4];

    // ---- GEMM1: h = T @ W1 + b1 ----
    #pragma unroll
    for (int nt = 0; nt < 8; nt++) {
        int col = nt * 8 + tg * 2;
        float2 bb = *(const float2*)(b1 + col);
        acc[nt][0] = bb.x; acc[nt][1] = bb.y;
        acc[nt][2] = bb.x; acc[nt][3] = bb.y;
        int cw = (nt * 8 + g) * WS;
        #pragma unroll
        for (int kt = 0; kt < 4; kt++) {
            int k0 = kt * 16 + tg * 2;
            uint32_t b0 = *(const uint32_t*)(sW1t + cw + k0);
            uint32_t b1r = *(const uint32_t*)(sW1t + cw + k0 + 8);
            hmma(acc[nt], a1f[kt], b0, b1r);
        }
    }

    // ---- tanh + repack C1 -> A2 fragments (pure registers) ----
    uint32_t a2f[4][4];
    #pragma unroll
    for (int kt = 0; kt < 4; kt++) {
        int e = 2 * kt;
        a2f[kt][0] = pack_h2(fast_tanh(acc[e][0]),     fast_tanh(acc[e][1]));
        a2f[kt][1] = pack_h2(fast_tanh(acc[e][2]),     fast_tanh(acc[e][3]));
        a2f[kt][2] = pack_h2(fast_tanh(acc[e + 1][0]), fast_tanh(acc[e + 1][1]));
        a2f[kt][3] = pack_h2(fast_tanh(acc[e + 1][2]), fast_tanh(acc[e + 1][3]));
    }

    // ---- GEMM2: y = H @ W2 + b2 ----
    #pragma unroll
    for (int nt = 0; nt < 8; nt++) {
        int col = nt * 8 + tg * 2;
        float2 bb = *(const float2*)(b2 + col);
        acc[nt][0] = bb.x; acc[nt][1] = bb.y;
        acc[nt][2] = bb.x; acc[nt][3] = bb.y;
        int cw = (nt * 8 + g) * WS;
        #pragma unroll
        for (int kt = 0; kt < 4; kt++) {
            int k0 = kt * 16 + tg * 2;
            uint32_t b0 = *(const uint32_t*)(sW2t + cw + k0);
            uint32_t b1r = *(const uint32_t*)(sW2t + cw + k0 + 8);
            hmma(acc[nt], a2f[kt], b0, b1r);
        }
    }

    // ---- store ----
    int gr0 = n0 + row0;
    int gr1 = n0 + row1;
    #pragma unroll
    for (int nt = 0; nt < 8; nt++) {
        int col = nt * 8 + tg * 2;
        if (out_half) {
            if (gr0 < NN)
                *(uint32_t*)(g_y0h + (size_t)gr0 * DD + col) =
                    pack_h2(acc[nt][0], acc[nt][1]);
            if (gr1 < NN)
                *(uint32_t*)(g_y0h + (size_t)gr1 * DD + col) =
                    pack_h2(acc[nt][2], acc[nt][3]);
        } else {
            if (gr0 < NN)
                *(float2*)(out + (size_t)gr0 * DD + col) =
                    make_float2(acc[nt][0], acc[nt][1]);
            if (gr1 < NN)
                *(float2*)(out + (size_t)gr1 * DD + col) =
                    make_float2(acc[nt][2], acc[nt][3]);
        }
    }
}

// ---------------------------------------------------------------------------
// launch — 7 kernels
// ---------------------------------------------------------------------------
extern "C" void kernel_launch(void* const* d_in, const int* in_sizes, int n_in,
                              void* d_out, int out_size) {
    const float* x    = (const float*)d_in[0];
    const int*   src  = (const int*)d_in[1];
    const int*   dst  = (const int*)d_in[2];
    const float* w1_0 = (const float*)d_in[3];
    const float* b1_0 = (const float*)d_in[4];
    const float* w2_0 = (const float*)d_in[5];
    const float* b2_0 = (const float*)d_in[6];
    const float* w1_1 = (const float*)d_in[7];
    const float* b1_1 = (const float*)d_in[8];
    const float* w2_1 = (const float*)d_in[9];
    const float* b2_1 = (const float*)d_in[10];
    float* out = (float*)d_out;

    const int edgeb = (NE + 255) / 256;
    const int gathb = (NN * 8 + 255) / 256;
    const int mlpb  = (NN + 63) / 64;

    convhist_kernel<<<edgeb, 256>>>(x, dst);
    scan_kernel<<<NCHUNK, SCAN_T>>>();
    fill_kernel<<<edgeb, 256>>>(src, dst);

    gather_kernel<<<gathb, 256>>>(/*in_scratch=*/0);
    mlp_kernel<<<mlpb, 128>>>(w1_0, b1_0, w2_0, b2_0, out, /*out_half=*/1);

    gather_kernel<<<gathb, 256>>>(/*in_scratch=*/1);
    mlp_kernel<<<mlpb, 128>>>(w1_1, b1_1, w2_1, b2_1, out, /*out_half=*/0);
}